// round 13
// baseline (speedup 1.0000x reference)
#include <cuda_runtime.h>
#include <cuda_fp16.h>
#include <math.h>

// Problem constants (fixed instance)
#define RR   4
#define NN   20000
#define NSRC 20000
#define DD   256
#define EE   640000
#define KK   16
#define SUBS 4          // sub-buckets per (r,dst)
#define SCAP 32         // capacity per sub-bucket
#define CAPT (SUBS * SCAP)   // 128 slots per (r,dst)
#define CMAX 128

// Static scratch (allocation-free rule)
__device__ int            g_cnt4[RR * NN * SUBS];
__device__ unsigned short g_slots16[(size_t)RR * NN * CAPT];
__device__ __half         g_H16[(size_t)NN * RR * DD];      // [N][R*D] fp16 (40MB)
__device__ __half         g_x16[(size_t)RR * NSRC * DD];    // fp16 x (40MB)

#define H2(u) (*(const __half2*)&(u))

// ---------------------------------------------------------------------------
// Per-relation fused prep (templated on relation RRI): 1875 blocks.
// bx%3 != 2 -> convert (1250 blocks, 2 uint4-groups/thread);
// bx%3 == 2 -> bucket (625 blocks, 4 edges/thread, 4-way sub-buckets).
template <int RRI>
__global__ __launch_bounds__(256) void prep_kernel(
    const float* __restrict__ x,
    const int*   __restrict__ src_idx,
    const int*   __restrict__ dst_idx)
{
    const int bx = blockIdx.x;
    if (bx % 3 != 2) {
        int conv_id = bx - (bx + 1) / 3;                   // 0..1249
        size_t base = (size_t)conv_id * 512 + threadIdx.x;
        const float4* xs = (const float4*)x + (size_t)RRI * (NSRC * DD / 4);
        uint4* xd = (uint4*)g_x16 + (size_t)RRI * (NSRC * DD / 8);
        float4 v0 = xs[2 * base];
        float4 v1 = xs[2 * base + 1];
        float4 v2 = xs[2 * (base + 256)];
        float4 v3 = xs[2 * (base + 256) + 1];
        __half2 h0 = __floats2half2_rn(v0.x, v0.y);
        __half2 h1 = __floats2half2_rn(v0.z, v0.w);
        __half2 h2 = __floats2half2_rn(v1.x, v1.y);
        __half2 h3 = __floats2half2_rn(v1.z, v1.w);
        uint4 pa; pa.x = *(unsigned*)&h0; pa.y = *(unsigned*)&h1;
        pa.z = *(unsigned*)&h2; pa.w = *(unsigned*)&h3;
        xd[base] = pa;
        __half2 h4 = __floats2half2_rn(v2.x, v2.y);
        __half2 h5 = __floats2half2_rn(v2.z, v2.w);
        __half2 h6 = __floats2half2_rn(v3.x, v3.y);
        __half2 h7 = __floats2half2_rn(v3.z, v3.w);
        uint4 pb; pb.x = *(unsigned*)&h4; pb.y = *(unsigned*)&h5;
        pb.z = *(unsigned*)&h6; pb.w = *(unsigned*)&h7;
        xd[base + 256] = pb;
    } else {
        int buck_id = bx / 3;                              // 0..624
        int base = buck_id * 1024 + threadIdx.x;
        const int* srcs = src_idx + (size_t)RRI * EE;
        const int* dsts = dst_idx + (size_t)RRI * EE;
        int s[4], dt[4];
        #pragma unroll
        for (int j = 0; j < 4; j++) {
            int e = base + j * 256;
            s[j]  = srcs[e];
            dt[j] = dsts[e];
        }
        #pragma unroll
        for (int j = 0; j < 4; j++) {
            int e = base + j * 256;
            int sub = e & (SUBS - 1);
            int b4 = (RRI * NN + dt[j]) * SUBS + sub;
            int rank = atomicAdd(&g_cnt4[b4], 1);
            if (rank < SCAP)
                g_slots16[(size_t)b4 * SCAP + rank] = (unsigned short)s[j];
        }
    }
}

// ---------------------------------------------------------------------------
// Per-relation agg: one WARP per node n. SMEM-resident softmax: logits go
// straight into swf (float), rewritten in place to exp then to half2 weights
// (same 4-byte slots). Only scalar max/sum live in registers -> low regcount,
// high occupancy for the latency-bound gather loop.
template <int RRI>
__global__ __launch_bounds__(256, 7) void agg_kernel(
    const float* __restrict__ d,    // [R, NSRC]
    const float* __restrict__ d1,
    const float* __restrict__ d2,
    const int*   __restrict__ split_p)
{
    const int warp = threadIdx.x >> 5;
    const int lane = threadIdx.x & 31;
    const int n = blockIdx.x * 8 + warp;

    __shared__ float    swf[8][CMAX];    // logit -> exp -> (as half2) weight
    __shared__ unsigned soff[8][CMAX];   // src*32 (uint4 row offsets)

    const int b = RRI * NN + n;
    int4 c4 = ((const int4*)g_cnt4)[b];
    int c0 = min(c4.x, SCAP), c1 = min(c4.y, SCAP);
    int c2 = min(c4.z, SCAP), c3 = min(c4.w, SCAP);
    const int pre1 = c0, pre2 = c0 + c1, pre3 = c0 + c1 + c2;
    const int cnt  = pre3 + c3;

    const int split = split_p ? __ldg(split_p) : 10000;
    const bool use1 = (n < split);

    const unsigned short* slot = g_slots16 + (size_t)b * CAPT;
    const float* dr  = d  + (size_t)RRI * NSRC;
    const float* d1r = d1 + (size_t)RRI * NSRC;
    const float* d2r = d2 + (size_t)RRI * NSRC;

    // Phase 1: slot mapping + logits into smem; running max in one register.
    float mloc = -1e30f;
    #pragma unroll
    for (int j = 0; j < 4; j++) {
        int i = lane + 32 * j;
        if (i < cnt) {
            int sub = (i >= pre1) + (i >= pre2) + (i >= pre3);
            int bs  = (sub == 0) ? 0 : ((sub == 1) ? pre1 : ((sub == 2) ? pre2 : pre3));
            int sv  = slot[sub * SCAP + (i - bs)];
            soff[warp][i] = (unsigned)sv * 32u;
            float dv = dr[sv];
            float l  = use1 ? (d1r[sv] / dv) : (-d2r[sv] / dv);
            swf[warp][i] = l;
            mloc = fmaxf(mloc, l);
        }
    }
    #pragma unroll
    for (int o = 16; o; o >>= 1) mloc = fmaxf(mloc, __shfl_xor_sync(0xffffffffu, mloc, o));

    // Phase 2: exp in place; running sum in one register.
    float sum = 0.f;
    #pragma unroll
    for (int j = 0; j < 4; j++) {
        int i = lane + 32 * j;
        if (i < cnt) {
            float e = __expf(swf[warp][i] - mloc);
            swf[warp][i] = e;
            sum += e;
        }
    }
    #pragma unroll
    for (int o = 16; o; o >>= 1) sum += __shfl_xor_sync(0xffffffffu, sum, o);
    const float winv = 1.f / fmaxf(sum, 1e-9f);

    // Phase 3: normalize and pack (w,w) half2 into the same slots.
    #pragma unroll
    for (int j = 0; j < 4; j++) {
        int i = lane + 32 * j;
        if (i < cnt)
            *(__half2*)&swf[warp][i] = __float2half2_rn(swf[warp][i] * winv);
    }
    __syncwarp();

    const __half2* swh = (const __half2*)&swf[warp][0];   // stride-4B half2 view
    const unsigned* sof = &soff[warp][0];
    const uint4* xr = (const uint4*)g_x16 + (size_t)RRI * NSRC * 32 + lane;
    float a0=0,a1=0,a2=0,a3=0,a4=0,a5=0,a6=0,a7=0;
    const __half2 z = __float2half2_rn(0.f);

    int i = 0;
    for (; i + 8 <= cnt; i += 8) {
        uint4 u0 = xr[sof[i]];
        uint4 u1 = xr[sof[i+1]];
        uint4 u2 = xr[sof[i+2]];
        uint4 u3 = xr[sof[i+3]];
        uint4 u4 = xr[sof[i+4]];
        uint4 u5 = xr[sof[i+5]];
        uint4 u6 = xr[sof[i+6]];
        uint4 u7 = xr[sof[i+7]];
        __half2 w0 = swh[i],   w1 = swh[i+1];
        __half2 w2 = swh[i+2], w3 = swh[i+3];
        __half2 w4 = swh[i+4], w5 = swh[i+5];
        __half2 w6 = swh[i+6], w7 = swh[i+7];
        __half2 c0h = z, c1h = z, c2h = z, c3h = z;
        __half2 e0h = z, e1h = z, e2h = z, e3h = z;
        c0h = __hfma2(w0, H2(u0.x), c0h); c1h = __hfma2(w0, H2(u0.y), c1h);
        c2h = __hfma2(w0, H2(u0.z), c2h); c3h = __hfma2(w0, H2(u0.w), c3h);
        c0h = __hfma2(w1, H2(u1.x), c0h); c1h = __hfma2(w1, H2(u1.y), c1h);
        c2h = __hfma2(w1, H2(u1.z), c2h); c3h = __hfma2(w1, H2(u1.w), c3h);
        c0h = __hfma2(w2, H2(u2.x), c0h); c1h = __hfma2(w2, H2(u2.y), c1h);
        c2h = __hfma2(w2, H2(u2.z), c2h); c3h = __hfma2(w2, H2(u2.w), c3h);
        c0h = __hfma2(w3, H2(u3.x), c0h); c1h = __hfma2(w3, H2(u3.y), c1h);
        c2h = __hfma2(w3, H2(u3.z), c2h); c3h = __hfma2(w3, H2(u3.w), c3h);
        e0h = __hfma2(w4, H2(u4.x), e0h); e1h = __hfma2(w4, H2(u4.y), e1h);
        e2h = __hfma2(w4, H2(u4.z), e2h); e3h = __hfma2(w4, H2(u4.w), e3h);
        e0h = __hfma2(w5, H2(u5.x), e0h); e1h = __hfma2(w5, H2(u5.y), e1h);
        e2h = __hfma2(w5, H2(u5.z), e2h); e3h = __hfma2(w5, H2(u5.w), e3h);
        e0h = __hfma2(w6, H2(u6.x), e0h); e1h = __hfma2(w6, H2(u6.y), e1h);
        e2h = __hfma2(w6, H2(u6.z), e2h); e3h = __hfma2(w6, H2(u6.w), e3h);
        e0h = __hfma2(w7, H2(u7.x), e0h); e1h = __hfma2(w7, H2(u7.y), e1h);
        e2h = __hfma2(w7, H2(u7.z), e2h); e3h = __hfma2(w7, H2(u7.w), e3h);
        float2 f0 = __half22float2(c0h), f1 = __half22float2(c1h);
        float2 f2 = __half22float2(c2h), f3 = __half22float2(c3h);
        float2 g0 = __half22float2(e0h), g1 = __half22float2(e1h);
        float2 g2 = __half22float2(e2h), g3 = __half22float2(e3h);
        a0 += f0.x + g0.x; a1 += f0.y + g0.y;
        a2 += f1.x + g1.x; a3 += f1.y + g1.y;
        a4 += f2.x + g2.x; a5 += f2.y + g2.y;
        a6 += f3.x + g3.x; a7 += f3.y + g3.y;
    }
    for (; i + 4 <= cnt; i += 4) {
        __half2 w0 = swh[i],   w1 = swh[i+1];
        __half2 w2 = swh[i+2], w3 = swh[i+3];
        uint4 u0 = xr[sof[i]];
        uint4 u1 = xr[sof[i+1]];
        uint4 u2 = xr[sof[i+2]];
        uint4 u3 = xr[sof[i+3]];
        __half2 c0h = z, c1h = z, c2h = z, c3h = z;
        c0h = __hfma2(w0, H2(u0.x), c0h); c1h = __hfma2(w0, H2(u0.y), c1h);
        c2h = __hfma2(w0, H2(u0.z), c2h); c3h = __hfma2(w0, H2(u0.w), c3h);
        c0h = __hfma2(w1, H2(u1.x), c0h); c1h = __hfma2(w1, H2(u1.y), c1h);
        c2h = __hfma2(w1, H2(u1.z), c2h); c3h = __hfma2(w1, H2(u1.w), c3h);
        c0h = __hfma2(w2, H2(u2.x), c0h); c1h = __hfma2(w2, H2(u2.y), c1h);
        c2h = __hfma2(w2, H2(u2.z), c2h); c3h = __hfma2(w2, H2(u2.w), c3h);
        c0h = __hfma2(w3, H2(u3.x), c0h); c1h = __hfma2(w3, H2(u3.y), c1h);
        c2h = __hfma2(w3, H2(u3.z), c2h); c3h = __hfma2(w3, H2(u3.w), c3h);
        float2 f0 = __half22float2(c0h), f1 = __half22float2(c1h);
        float2 f2 = __half22float2(c2h), f3 = __half22float2(c3h);
        a0 += f0.x; a1 += f0.y; a2 += f1.x; a3 += f1.y;
        a4 += f2.x; a5 += f2.y; a6 += f3.x; a7 += f3.y;
    }
    for (; i < cnt; i++) {
        __half2 w0 = swh[i];
        uint4 u0 = xr[sof[i]];
        float2 f0 = __half22float2(__hmul2(w0, H2(u0.x)));
        float2 f1 = __half22float2(__hmul2(w0, H2(u0.y)));
        float2 f2 = __half22float2(__hmul2(w0, H2(u0.z)));
        float2 f3 = __half22float2(__hmul2(w0, H2(u0.w)));
        a0 += f0.x; a1 += f0.y; a2 += f1.x; a3 += f1.y;
        a4 += f2.x; a5 += f2.y; a6 += f3.x; a7 += f3.y;
    }

    __half2 h0 = __floats2half2_rn(a0, a1);
    __half2 h1 = __floats2half2_rn(a2, a3);
    __half2 h2 = __floats2half2_rn(a4, a5);
    __half2 h3 = __floats2half2_rn(a6, a7);
    uint4 packed;
    packed.x = *(const unsigned*)&h0;
    packed.y = *(const unsigned*)&h1;
    packed.z = *(const unsigned*)&h2;
    packed.w = *(const unsigned*)&h3;
    ((uint4*)(g_H16 + ((size_t)n * RR + RRI) * DD))[lane] = packed;
}

// ---------------------------------------------------------------------------
// One block per node. Thread t owns 4 elems (uint2). Squared diffs in regs as
// half2; s-accum in half2 split partials merged in fp32. 32-bit H indexing.
__global__ __launch_bounds__(256) void mask_kernel(
    const int* __restrict__ cand,   // [N, K]
    float*     __restrict__ out)    // [N, D]
{
    const int n = blockIdx.x;
    const int t = threadIdx.x;
    const int lane = t & 31, w = t >> 5;

    __shared__ unsigned coff[KK];
    __shared__ __half   wsumh[8][KK];
    __shared__ __half2  satth[KK];
    __shared__ float    sval[RR * DD];

    if (t < KK) coff[t] = (unsigned)cand[n * KK + t] * 256u;
    __syncthreads();

    const uint2* Hb = (const uint2*)g_H16 + t;
    const uint2 ownu = Hb[(unsigned)n * 256u];
    const __half2 own0 = H2(ownu.x);
    const __half2 own1 = H2(ownu.y);

    __half2 sq0[KK], sq1[KK];
    __half2 ph[KK];
    #pragma unroll
    for (int k = 0; k < KK; k++) {
        uint2 cu = Hb[coff[k]];
        __half2 d0 = __hsub2(own0, H2(cu.x));
        __half2 d1 = __hsub2(own1, H2(cu.y));
        __half2 q0 = __hmul2(d0, d0);
        __half2 q1 = __hmul2(d1, d1);
        sq0[k] = q0; sq1[k] = q1;
        ph[k] = __hadd2(q0, q1);
    }

    __half2 pp[KK / 2];
    #pragma unroll
    for (int j = 0; j < KK / 2; j++) {
        __half a = __hadd(__low2half(ph[2*j]),     __high2half(ph[2*j]));
        __half b = __hadd(__low2half(ph[2*j + 1]), __high2half(ph[2*j + 1]));
        pp[j] = __halves2half2(a, b);
    }
    #pragma unroll
    for (int j = 0; j < KK / 2; j++) {
        unsigned v = *(unsigned*)&pp[j];
        #pragma unroll
        for (int o = 16; o; o >>= 1) {
            unsigned u = __shfl_xor_sync(0xffffffffu, v, o);
            __half2 hv = __hadd2(*(__half2*)&v, *(__half2*)&u);
            v = *(unsigned*)&hv;
        }
        if (lane == 0) ((__half2*)&wsumh[w][0])[j] = *(__half2*)&v;
    }
    __syncthreads();

    if (t < 32) {
        float dist = 1e30f;
        if (t < KK) {
            float s = 0.f;
            #pragma unroll
            for (int ww = 0; ww < 8; ww++) s += __half2float(wsumh[ww][t]);
            dist = sqrtf(s);
        }
        float mn = dist;
        #pragma unroll
        for (int o = 16; o; o >>= 1) mn = fminf(mn, __shfl_xor_sync(0xffffffffu, mn, o));
        float e = (t < KK) ? __expf(mn - dist) : 0.f;
        float s = e;
        #pragma unroll
        for (int o = 16; o; o >>= 1) s += __shfl_xor_sync(0xffffffffu, s, o);
        if (t < KK) satth[t] = __float2half2_rn(e / s);
    }
    __syncthreads();

    const __half2 z = __float2half2_rn(0.f);
    __half2 pa0 = z, pa1 = z, pb0 = z, pb1 = z;
    #pragma unroll
    for (int k = 0; k < 8; k++) {
        __half2 a = satth[k];
        pa0 = __hfma2(a, sq0[k], pa0);
        pa1 = __hfma2(a, sq1[k], pa1);
    }
    #pragma unroll
    for (int k = 8; k < KK; k++) {
        __half2 a = satth[k];
        pb0 = __hfma2(a, sq0[k], pb0);
        pb1 = __hfma2(a, sq1[k], pb1);
    }
    float2 fa0 = __half22float2(pa0), fb0 = __half22float2(pb0);
    float2 fa1 = __half22float2(pa1), fb1 = __half22float2(pb1);
    float sx = fa0.x + fb0.x, sy = fa0.y + fb0.y;
    float sz = fa1.x + fb1.x, sw_ = fa1.y + fb1.y;

    float2 o0 = __half22float2(own0);
    float2 o1 = __half22float2(own1);
    float4 val;
    val.x = o0.x * __expf(-sx);
    val.y = o0.y * __expf(-sy);
    val.z = o1.x * __expf(-sz);
    val.w = o1.y * __expf(-sw_);
    ((float4*)sval)[t] = val;
    __syncthreads();

    if (t < 64) {
        float4 b0 = ((float4*)sval)[t];
        float4 b1 = ((float4*)sval)[t + 64];
        float4 b2 = ((float4*)sval)[t + 128];
        float4 b3 = ((float4*)sval)[t + 192];
        float4 o;
        o.x = b0.x + b1.x + b2.x + b3.x;
        o.y = b0.y + b1.y + b2.y + b3.y;
        o.z = b0.z + b1.z + b2.z + b3.z;
        o.w = b0.w + b1.w + b2.w + b3.w;
        ((float4*)(out + (size_t)n * DD))[t] = o;
    }
}

// ---------------------------------------------------------------------------
extern "C" void kernel_launch(void* const* d_in, const int* in_sizes, int n_in,
                              void* d_out, int out_size)
{
    const float* x    = (const float*)d_in[0];
    const float* d    = (const float*)d_in[1];
    const float* d1   = (const float*)d_in[2];
    const float* d2   = (const float*)d_in[3];
    const int*   src  = (const int*)d_in[4];
    const int*   dst  = (const int*)d_in[5];
    const int*   cand = (const int*)d_in[6];
    const int*   split = (n_in >= 8) ? (const int*)d_in[7] : nullptr;
    float* out = (float*)d_out;

    (void)in_sizes; (void)out_size;

    static cudaStream_t st[3] = {nullptr, nullptr, nullptr};
    static cudaEvent_t  evRoot = nullptr, evDone[3] = {nullptr, nullptr, nullptr};
    static void* cnt_ptr = nullptr;
    if (st[0] == nullptr) {
        for (int i = 0; i < 3; i++) {
            cudaStreamCreateWithFlags(&st[i], cudaStreamNonBlocking);
            cudaEventCreateWithFlags(&evDone[i], cudaEventDisableTiming);
        }
        cudaEventCreateWithFlags(&evRoot, cudaEventDisableTiming);
        cudaGetSymbolAddress(&cnt_ptr, g_cnt4);
    }

    cudaMemsetAsync(cnt_ptr, 0, (size_t)RR * NN * SUBS * sizeof(int), 0);
    cudaEventRecord(evRoot, 0);

    // relations 1..3 on side streams (fork)
    cudaStreamWaitEvent(st[0], evRoot, 0);
    prep_kernel<1><<<1875, 256, 0, st[0]>>>(x, src, dst);
    agg_kernel<1><<<NN / 8, 256, 0, st[0]>>>(d, d1, d2, split);
    cudaEventRecord(evDone[0], st[0]);

    cudaStreamWaitEvent(st[1], evRoot, 0);
    prep_kernel<2><<<1875, 256, 0, st[1]>>>(x, src, dst);
    agg_kernel<2><<<NN / 8, 256, 0, st[1]>>>(d, d1, d2, split);
    cudaEventRecord(evDone[1], st[1]);

    cudaStreamWaitEvent(st[2], evRoot, 0);
    prep_kernel<3><<<1875, 256, 0, st[2]>>>(x, src, dst);
    agg_kernel<3><<<NN / 8, 256, 0, st[2]>>>(d, d1, d2, split);
    cudaEventRecord(evDone[2], st[2]);

    // relation 0 on the main stream
    prep_kernel<0><<<1875, 256, 0, 0>>>(x, src, dst);
    agg_kernel<0><<<NN / 8, 256, 0, 0>>>(d, d1, d2, split);

    // join, then mask
    for (int r = 0; r < 3; r++) cudaStreamWaitEvent(0, evDone[r], 0);
    mask_kernel<<<NN, 256, 0, 0>>>(cand, out);
}

// round 14
// speedup vs baseline: 1.2252x; 1.2252x over previous
#include <cuda_runtime.h>
#include <cuda_fp16.h>
#include <math.h>

// Problem constants (fixed instance)
#define RR   4
#define NN   20000
#define NSRC 20000
#define DD   256
#define EE   640000
#define KK   16
#define SUBS 4          // sub-buckets per (r,dst)
#define SCAP 32         // capacity per sub-bucket
#define CAPT (SUBS * SCAP)   // 128 slots per (r,dst)
#define CMAX 128

// Static scratch (allocation-free rule)
__device__ int            g_cnt4[RR * NN * SUBS];
__device__ unsigned short g_slots16[(size_t)RR * NN * CAPT];
__device__ __half         g_H16[(size_t)NN * RR * DD];      // [N][R*D] fp16 (40MB)
__device__ __half         g_x16[(size_t)RR * NSRC * DD];    // fp16 x (40MB)

#define H2(u) (*(const __half2*)&(u))

// ---------------------------------------------------------------------------
// Per-relation fused prep: 1875 blocks. bx%3 != 2 -> convert (1250 blocks,
// 2 uint4-groups/thread); bx%3 == 2 -> bucket (625 blocks, 4 edges/thread,
// 4-way sub-buckets by e&3).
__global__ __launch_bounds__(256) void prep_kernel(
    const float* __restrict__ x,
    const int*   __restrict__ src_idx,
    const int*   __restrict__ dst_idx,
    const int    rr)
{
    const int bx = blockIdx.x;
    if (bx % 3 != 2) {
        int conv_id = bx - (bx + 1) / 3;                   // 0..1249
        size_t base = (size_t)conv_id * 512 + threadIdx.x;
        const float4* xs = (const float4*)x + (size_t)rr * (NSRC * DD / 4);
        uint4* xd = (uint4*)g_x16 + (size_t)rr * (NSRC * DD / 8);
        float4 v0 = xs[2 * base];
        float4 v1 = xs[2 * base + 1];
        float4 v2 = xs[2 * (base + 256)];
        float4 v3 = xs[2 * (base + 256) + 1];
        __half2 h0 = __floats2half2_rn(v0.x, v0.y);
        __half2 h1 = __floats2half2_rn(v0.z, v0.w);
        __half2 h2 = __floats2half2_rn(v1.x, v1.y);
        __half2 h3 = __floats2half2_rn(v1.z, v1.w);
        uint4 pa; pa.x = *(unsigned*)&h0; pa.y = *(unsigned*)&h1;
        pa.z = *(unsigned*)&h2; pa.w = *(unsigned*)&h3;
        xd[base] = pa;
        __half2 h4 = __floats2half2_rn(v2.x, v2.y);
        __half2 h5 = __floats2half2_rn(v2.z, v2.w);
        __half2 h6 = __floats2half2_rn(v3.x, v3.y);
        __half2 h7 = __floats2half2_rn(v3.z, v3.w);
        uint4 pb; pb.x = *(unsigned*)&h4; pb.y = *(unsigned*)&h5;
        pb.z = *(unsigned*)&h6; pb.w = *(unsigned*)&h7;
        xd[base + 256] = pb;
    } else {
        int buck_id = bx / 3;                              // 0..624
        int base = buck_id * 1024 + threadIdx.x;
        const int* srcs = src_idx + (size_t)rr * EE;
        const int* dsts = dst_idx + (size_t)rr * EE;
        int s[4], dt[4];
        #pragma unroll
        for (int j = 0; j < 4; j++) {
            int e = base + j * 256;
            s[j]  = srcs[e];
            dt[j] = dsts[e];
        }
        #pragma unroll
        for (int j = 0; j < 4; j++) {
            int e = base + j * 256;
            int sub = e & (SUBS - 1);
            int b4 = (rr * NN + dt[j]) * SUBS + sub;
            int rank = atomicAdd(&g_cnt4[b4], 1);
            if (rank < SCAP)
                g_slots16[(size_t)b4 * SCAP + rank] = (unsigned short)s[j];
        }
    }
}

// ---------------------------------------------------------------------------
// Per-relation agg: one WARP per node n (grid 2500 x 8 warps). Register-
// resident softmax (r11-proven layout), 8-wide uint4 fp16 gather with two
// independent half2 accumulator groups.
__global__ __launch_bounds__(256) void agg_kernel(
    const float* __restrict__ d,    // [R, NSRC]
    const float* __restrict__ d1,
    const float* __restrict__ d2,
    const int*   __restrict__ split_p,
    const int    rr)
{
    const int warp = threadIdx.x >> 5;
    const int lane = threadIdx.x & 31;
    const int n = blockIdx.x * 8 + warp;

    __shared__ __half2  swh[8][CMAX];
    __shared__ unsigned soff[8][CMAX];

    const int b = rr * NN + n;
    int4 c4 = ((const int4*)g_cnt4)[b];
    int c0 = min(c4.x, SCAP), c1 = min(c4.y, SCAP);
    int c2 = min(c4.z, SCAP), c3 = min(c4.w, SCAP);
    const int pre1 = c0, pre2 = c0 + c1, pre3 = c0 + c1 + c2;
    const int cnt  = pre3 + c3;

    const int split = split_p ? __ldg(split_p) : 10000;
    const bool use1 = (n < split);

    const unsigned short* slot = g_slots16 + (size_t)b * CAPT;

    float l[4];
    int   s[4];
    #pragma unroll
    for (int j = 0; j < 4; j++) {
        int i = lane + 32 * j;
        l[j] = -1e30f; s[j] = 0;
        if (i < cnt) {
            int sub  = (i >= pre1) + (i >= pre2) + (i >= pre3);
            int bs = (sub == 0) ? 0 : ((sub == 1) ? pre1 : ((sub == 2) ? pre2 : pre3));
            int sv = slot[sub * SCAP + (i - bs)];
            s[j] = sv;
            float dv = d[rr * NSRC + sv];
            l[j] = use1 ? (d1[rr * NSRC + sv] / dv)
                        : (-d2[rr * NSRC + sv] / dv);
        }
    }
    float m = fmaxf(fmaxf(l[0], l[1]), fmaxf(l[2], l[3]));
    #pragma unroll
    for (int o = 16; o; o >>= 1) m = fmaxf(m, __shfl_xor_sync(0xffffffffu, m, o));

    float e[4];
    float sum = 0.f;
    #pragma unroll
    for (int j = 0; j < 4; j++) {
        e[j] = (lane + 32 * j < cnt) ? __expf(l[j] - m) : 0.f;
        sum += e[j];
    }
    #pragma unroll
    for (int o = 16; o; o >>= 1) sum += __shfl_xor_sync(0xffffffffu, sum, o);
    const float winv = 1.f / fmaxf(sum, 1e-9f);

    #pragma unroll
    for (int j = 0; j < 4; j++) {
        int i = lane + 32 * j;
        if (i < cnt) {
            swh[warp][i]  = __float2half2_rn(e[j] * winv);
            soff[warp][i] = (unsigned)s[j] * 32u;
        }
    }
    __syncwarp();

    const uint4* xr = (const uint4*)g_x16 + (size_t)rr * NSRC * 32 + lane;
    float a0=0,a1=0,a2=0,a3=0,a4=0,a5=0,a6=0,a7=0;
    const __half2 z = __float2half2_rn(0.f);

    int i = 0;
    for (; i + 8 <= cnt; i += 8) {
        uint4 u0 = xr[soff[warp][i]];
        uint4 u1 = xr[soff[warp][i+1]];
        uint4 u2 = xr[soff[warp][i+2]];
        uint4 u3 = xr[soff[warp][i+3]];
        uint4 u4 = xr[soff[warp][i+4]];
        uint4 u5 = xr[soff[warp][i+5]];
        uint4 u6 = xr[soff[warp][i+6]];
        uint4 u7 = xr[soff[warp][i+7]];
        __half2 w0 = swh[warp][i],   w1 = swh[warp][i+1];
        __half2 w2 = swh[warp][i+2], w3 = swh[warp][i+3];
        __half2 w4 = swh[warp][i+4], w5 = swh[warp][i+5];
        __half2 w6 = swh[warp][i+6], w7 = swh[warp][i+7];
        __half2 c0h = z, c1h = z, c2h = z, c3h = z;
        __half2 e0h = z, e1h = z, e2h = z, e3h = z;
        c0h = __hfma2(w0, H2(u0.x), c0h); c1h = __hfma2(w0, H2(u0.y), c1h);
        c2h = __hfma2(w0, H2(u0.z), c2h); c3h = __hfma2(w0, H2(u0.w), c3h);
        c0h = __hfma2(w1, H2(u1.x), c0h); c1h = __hfma2(w1, H2(u1.y), c1h);
        c2h = __hfma2(w1, H2(u1.z), c2h); c3h = __hfma2(w1, H2(u1.w), c3h);
        c0h = __hfma2(w2, H2(u2.x), c0h); c1h = __hfma2(w2, H2(u2.y), c1h);
        c2h = __hfma2(w2, H2(u2.z), c2h); c3h = __hfma2(w2, H2(u2.w), c3h);
        c0h = __hfma2(w3, H2(u3.x), c0h); c1h = __hfma2(w3, H2(u3.y), c1h);
        c2h = __hfma2(w3, H2(u3.z), c2h); c3h = __hfma2(w3, H2(u3.w), c3h);
        e0h = __hfma2(w4, H2(u4.x), e0h); e1h = __hfma2(w4, H2(u4.y), e1h);
        e2h = __hfma2(w4, H2(u4.z), e2h); e3h = __hfma2(w4, H2(u4.w), e3h);
        e0h = __hfma2(w5, H2(u5.x), e0h); e1h = __hfma2(w5, H2(u5.y), e1h);
        e2h = __hfma2(w5, H2(u5.z), e2h); e3h = __hfma2(w5, H2(u5.w), e3h);
        e0h = __hfma2(w6, H2(u6.x), e0h); e1h = __hfma2(w6, H2(u6.y), e1h);
        e2h = __hfma2(w6, H2(u6.z), e2h); e3h = __hfma2(w6, H2(u6.w), e3h);
        e0h = __hfma2(w7, H2(u7.x), e0h); e1h = __hfma2(w7, H2(u7.y), e1h);
        e2h = __hfma2(w7, H2(u7.z), e2h); e3h = __hfma2(w7, H2(u7.w), e3h);
        float2 f0 = __half22float2(c0h), f1 = __half22float2(c1h);
        float2 f2 = __half22float2(c2h), f3 = __half22float2(c3h);
        float2 g0 = __half22float2(e0h), g1 = __half22float2(e1h);
        float2 g2 = __half22float2(e2h), g3 = __half22float2(e3h);
        a0 += f0.x + g0.x; a1 += f0.y + g0.y;
        a2 += f1.x + g1.x; a3 += f1.y + g1.y;
        a4 += f2.x + g2.x; a5 += f2.y + g2.y;
        a6 += f3.x + g3.x; a7 += f3.y + g3.y;
    }
    for (; i + 4 <= cnt; i += 4) {
        __half2 w0 = swh[warp][i],   w1 = swh[warp][i+1];
        __half2 w2 = swh[warp][i+2], w3 = swh[warp][i+3];
        uint4 u0 = xr[soff[warp][i]];
        uint4 u1 = xr[soff[warp][i+1]];
        uint4 u2 = xr[soff[warp][i+2]];
        uint4 u3 = xr[soff[warp][i+3]];
        __half2 c0h = z, c1h = z, c2h = z, c3h = z;
        c0h = __hfma2(w0, H2(u0.x), c0h); c1h = __hfma2(w0, H2(u0.y), c1h);
        c2h = __hfma2(w0, H2(u0.z), c2h); c3h = __hfma2(w0, H2(u0.w), c3h);
        c0h = __hfma2(w1, H2(u1.x), c0h); c1h = __hfma2(w1, H2(u1.y), c1h);
        c2h = __hfma2(w1, H2(u1.z), c2h); c3h = __hfma2(w1, H2(u1.w), c3h);
        c0h = __hfma2(w2, H2(u2.x), c0h); c1h = __hfma2(w2, H2(u2.y), c1h);
        c2h = __hfma2(w2, H2(u2.z), c2h); c3h = __hfma2(w2, H2(u2.w), c3h);
        c0h = __hfma2(w3, H2(u3.x), c0h); c1h = __hfma2(w3, H2(u3.y), c1h);
        c2h = __hfma2(w3, H2(u3.z), c2h); c3h = __hfma2(w3, H2(u3.w), c3h);
        float2 f0 = __half22float2(c0h), f1 = __half22float2(c1h);
        float2 f2 = __half22float2(c2h), f3 = __half22float2(c3h);
        a0 += f0.x; a1 += f0.y; a2 += f1.x; a3 += f1.y;
        a4 += f2.x; a5 += f2.y; a6 += f3.x; a7 += f3.y;
    }
    for (; i < cnt; i++) {
        __half2 w0 = swh[warp][i];
        uint4 u0 = xr[soff[warp][i]];
        float2 f0 = __half22float2(__hmul2(w0, H2(u0.x)));
        float2 f1 = __half22float2(__hmul2(w0, H2(u0.y)));
        float2 f2 = __half22float2(__hmul2(w0, H2(u0.z)));
        float2 f3 = __half22float2(__hmul2(w0, H2(u0.w)));
        a0 += f0.x; a1 += f0.y; a2 += f1.x; a3 += f1.y;
        a4 += f2.x; a5 += f2.y; a6 += f3.x; a7 += f3.y;
    }

    __half2 h0 = __floats2half2_rn(a0, a1);
    __half2 h1 = __floats2half2_rn(a2, a3);
    __half2 h2 = __floats2half2_rn(a4, a5);
    __half2 h3 = __floats2half2_rn(a6, a7);
    uint4 packed;
    packed.x = *(const unsigned*)&h0;
    packed.y = *(const unsigned*)&h1;
    packed.z = *(const unsigned*)&h2;
    packed.w = *(const unsigned*)&h3;
    ((uint4*)(g_H16 + ((size_t)n * RR + rr) * DD))[lane] = packed;
}

// ---------------------------------------------------------------------------
// One block per node. Thread t owns 4 elems (uint2). Candidate loads issued
// in groups of 4 ahead of the arithmetic (bounded prefetch). Squared diffs in
// regs as half2; s-accum in half2 split partials merged in fp32.
__global__ __launch_bounds__(256) void mask_kernel(
    const int* __restrict__ cand,   // [N, K]
    float*     __restrict__ out)    // [N, D]
{
    const int n = blockIdx.x;
    const int t = threadIdx.x;
    const int lane = t & 31, w = t >> 5;

    __shared__ unsigned coff[KK];
    __shared__ __half   wsumh[8][KK];
    __shared__ __half2  satth[KK];
    __shared__ float    sval[RR * DD];

    if (t < KK) coff[t] = (unsigned)cand[n * KK + t] * 256u;
    __syncthreads();

    const uint2* Hb = (const uint2*)g_H16 + t;
    const uint2 ownu = Hb[(unsigned)n * 256u];
    const __half2 own0 = H2(ownu.x);
    const __half2 own1 = H2(ownu.y);

    __half2 sq0[KK], sq1[KK];
    __half2 ph[KK];
    #pragma unroll
    for (int kb = 0; kb < KK; kb += 4) {
        // issue 4 independent loads first
        uint2 cu0 = Hb[coff[kb]];
        uint2 cu1 = Hb[coff[kb + 1]];
        uint2 cu2 = Hb[coff[kb + 2]];
        uint2 cu3 = Hb[coff[kb + 3]];
        uint2 cus[4] = {cu0, cu1, cu2, cu3};
        #pragma unroll
        for (int j = 0; j < 4; j++) {
            int k = kb + j;
            __half2 d0 = __hsub2(own0, H2(cus[j].x));
            __half2 d1 = __hsub2(own1, H2(cus[j].y));
            __half2 q0 = __hmul2(d0, d0);
            __half2 q1 = __hmul2(d1, d1);
            sq0[k] = q0; sq1[k] = q1;
            ph[k] = __hadd2(q0, q1);
        }
    }

    __half2 pp[KK / 2];
    #pragma unroll
    for (int j = 0; j < KK / 2; j++) {
        __half a = __hadd(__low2half(ph[2*j]),     __high2half(ph[2*j]));
        __half b = __hadd(__low2half(ph[2*j + 1]), __high2half(ph[2*j + 1]));
        pp[j] = __halves2half2(a, b);
    }
    #pragma unroll
    for (int j = 0; j < KK / 2; j++) {
        unsigned v = *(unsigned*)&pp[j];
        #pragma unroll
        for (int o = 16; o; o >>= 1) {
            unsigned u = __shfl_xor_sync(0xffffffffu, v, o);
            __half2 hv = __hadd2(*(__half2*)&v, *(__half2*)&u);
            v = *(unsigned*)&hv;
        }
        if (lane == 0) ((__half2*)&wsumh[w][0])[j] = *(__half2*)&v;
    }
    __syncthreads();

    if (t < 32) {
        float dist = 1e30f;
        if (t < KK) {
            float s = 0.f;
            #pragma unroll
            for (int ww = 0; ww < 8; ww++) s += __half2float(wsumh[ww][t]);
            dist = sqrtf(s);
        }
        float mn = dist;
        #pragma unroll
        for (int o = 16; o; o >>= 1) mn = fminf(mn, __shfl_xor_sync(0xffffffffu, mn, o));
        float e = (t < KK) ? __expf(mn - dist) : 0.f;
        float s = e;
        #pragma unroll
        for (int o = 16; o; o >>= 1) s += __shfl_xor_sync(0xffffffffu, s, o);
        if (t < KK) satth[t] = __float2half2_rn(e / s);
    }
    __syncthreads();

    const __half2 z = __float2half2_rn(0.f);
    __half2 pa0 = z, pa1 = z, pb0 = z, pb1 = z;
    #pragma unroll
    for (int k = 0; k < 8; k++) {
        __half2 a = satth[k];
        pa0 = __hfma2(a, sq0[k], pa0);
        pa1 = __hfma2(a, sq1[k], pa1);
    }
    #pragma unroll
    for (int k = 8; k < KK; k++) {
        __half2 a = satth[k];
        pb0 = __hfma2(a, sq0[k], pb0);
        pb1 = __hfma2(a, sq1[k], pb1);
    }
    float2 fa0 = __half22float2(pa0), fb0 = __half22float2(pb0);
    float2 fa1 = __half22float2(pa1), fb1 = __half22float2(pb1);
    float sx = fa0.x + fb0.x, sy = fa0.y + fb0.y;
    float sz = fa1.x + fb1.x, sw_ = fa1.y + fb1.y;

    float2 o0 = __half22float2(own0);
    float2 o1 = __half22float2(own1);
    float4 val;
    val.x = o0.x * __expf(-sx);
    val.y = o0.y * __expf(-sy);
    val.z = o1.x * __expf(-sz);
    val.w = o1.y * __expf(-sw_);
    ((float4*)sval)[t] = val;
    __syncthreads();

    if (t < 64) {
        float4 b0 = ((float4*)sval)[t];
        float4 b1 = ((float4*)sval)[t + 64];
        float4 b2 = ((float4*)sval)[t + 128];
        float4 b3 = ((float4*)sval)[t + 192];
        float4 o;
        o.x = b0.x + b1.x + b2.x + b3.x;
        o.y = b0.y + b1.y + b2.y + b3.y;
        o.z = b0.z + b1.z + b2.z + b3.z;
        o.w = b0.w + b1.w + b2.w + b3.w;
        ((float4*)(out + (size_t)n * DD))[t] = o;
    }
}

// ---------------------------------------------------------------------------
extern "C" void kernel_launch(void* const* d_in, const int* in_sizes, int n_in,
                              void* d_out, int out_size)
{
    const float* x    = (const float*)d_in[0];
    const float* d    = (const float*)d_in[1];
    const float* d1   = (const float*)d_in[2];
    const float* d2   = (const float*)d_in[3];
    const int*   src  = (const int*)d_in[4];
    const int*   dst  = (const int*)d_in[5];
    const int*   cand = (const int*)d_in[6];
    const int*   split = (n_in >= 8) ? (const int*)d_in[7] : nullptr;
    float* out = (float*)d_out;

    (void)in_sizes; (void)out_size;

    static cudaStream_t st[3] = {nullptr, nullptr, nullptr};
    static cudaEvent_t  evRoot = nullptr, evDone[3] = {nullptr, nullptr, nullptr};
    static void* cnt_ptr = nullptr;
    if (st[0] == nullptr) {
        for (int i = 0; i < 3; i++) {
            cudaStreamCreateWithFlags(&st[i], cudaStreamNonBlocking);
            cudaEventCreateWithFlags(&evDone[i], cudaEventDisableTiming);
        }
        cudaEventCreateWithFlags(&evRoot, cudaEventDisableTiming);
        cudaGetSymbolAddress(&cnt_ptr, g_cnt4);
    }

    cudaMemsetAsync(cnt_ptr, 0, (size_t)RR * NN * SUBS * sizeof(int), 0);
    cudaEventRecord(evRoot, 0);

    // relations 1..3 on side streams (fork)
    for (int r = 1; r < 4; r++) {
        cudaStreamWaitEvent(st[r-1], evRoot, 0);
        prep_kernel<<<1875, 256, 0, st[r-1]>>>(x, src, dst, r);
        agg_kernel<<<NN / 8, 256, 0, st[r-1]>>>(d, d1, d2, split, r);
        cudaEventRecord(evDone[r-1], st[r-1]);
    }
    // relation 0 on the main stream
    prep_kernel<<<1875, 256, 0, 0>>>(x, src, dst, 0);
    agg_kernel<<<NN / 8, 256, 0, 0>>>(d, d1, d2, split, 0);

    // join, then mask
    for (int r = 0; r < 3; r++) cudaStreamWaitEvent(0, evDone[r], 0);
    mask_kernel<<<NN, 256, 0, 0>>>(cand, out);
}